// round 13
// baseline (speedup 1.0000x reference)
#include <cuda_runtime.h>
#include <cuda_bf16.h>
#include <cstdint>

#define DEVINL __device__ __forceinline__

namespace {

constexpr int Bb = 2, Hh = 16, Ss = 2048, Dd = 128;
constexpr int TM = 128;           // query tile
constexpr int TN = 128;           // key tile
constexpr int NKT = Ss / TN;      // 16
constexpr int NTHREADS = 256;     // 8 warps: 4 row-strips(32) x 2 t-halves
constexpr int ROWB = 272;         // 128 bf16 * 2B + 16B pad (conflict-free ldmatrix)
constexpr int TILE_B = 128 * ROWB;            // 34816
constexpr uint32_t SMEM_BYTES = 6 * TILE_B;   // 208896 (QH QL KH KL VH VL)

constexpr size_t NELEM = (size_t)Bb * Hh * Ss * Dd;  // 8,388,608 per tensor

}  // namespace

// 64 MB of pre-converted bf16 hi/lo planes for K and V (static scratch — legal)
__device__ __align__(16) __nv_bfloat16 g_KH[NELEM];
__device__ __align__(16) __nv_bfloat16 g_KL[NELEM];
__device__ __align__(16) __nv_bfloat16 g_VH[NELEM];
__device__ __align__(16) __nv_bfloat16 g_VL[NELEM];

namespace {

DEVINL uint32_t smem_u32(const void* p) {
  uint32_t a;
  asm("{ .reg .u64 t; cvta.to.shared.u64 t, %1; cvt.u32.u64 %0, t; }" : "=r"(a) : "l"(p));
  return a;
}

DEVINL uint32_t toff(int r, int c) { return (uint32_t)(r * ROWB + c * 2); }

// ---------------- fp32 -> bf16 hi/lo split ----------------
DEVINL void split2(float x, __nv_bfloat16& h, __nv_bfloat16& l) {
  h = __float2bfloat16(x);
  l = __float2bfloat16(x - __bfloat162float(h));
}
DEVINL uint32_t pack2(__nv_bfloat16 lo_el, __nv_bfloat16 hi_el) {
  return ((uint32_t)__bfloat16_as_ushort(hi_el) << 16) | (uint32_t)__bfloat16_as_ushort(lo_el);
}

// store 4 consecutive cols of one row into hi/lo tiles (8B chunks)
DEVINL void store_hl4(char* hB, char* lB, int row, int col, float4 val) {
  __nv_bfloat16 h0, h1, h2, h3, l0, l1, l2, l3;
  split2(val.x, h0, l0); split2(val.y, h1, l1);
  split2(val.z, h2, l2); split2(val.w, h3, l3);
  uint32_t off = toff(row, col);
  *reinterpret_cast<uint2*>(hB + off) = make_uint2(pack2(h0, h1), pack2(h2, h3));
  *reinterpret_cast<uint2*>(lB + off) = make_uint2(pack2(l0, l1), pack2(l2, l3));
}

// ---------------- cp.async helpers ----------------
DEVINL void cp16(uint32_t dst, const void* src) {
  asm volatile("cp.async.cg.shared.global [%0], [%1], 16;" :: "r"(dst), "l"(src));
}
#define CP_COMMIT()  asm volatile("cp.async.commit_group;" ::: "memory")
#define CP_WAIT1()   asm volatile("cp.async.wait_group 1;" ::: "memory")
#define CP_WAIT0()   asm volatile("cp.async.wait_group 0;" ::: "memory")

// copy one [128 x 128] bf16 hi/lo tile pair gmem -> padded smem (8 cp.async/thread each)
DEVINL void load_tile_pair(uint32_t dstH, uint32_t dstL,
                           const __nv_bfloat16* srcH, const __nv_bfloat16* srcL,
                           int tid) {
#pragma unroll
  for (int i = 0; i < 8; ++i) {
    int c = tid + i * NTHREADS;       // chunk id: 2048 chunks of 16B
    int row = c >> 4, ch = c & 15;
    cp16(dstH + (uint32_t)(row * ROWB + ch * 16), srcH + row * Dd + ch * 8);
    cp16(dstL + (uint32_t)(row * ROWB + ch * 16), srcL + row * Dd + ch * 8);
  }
}

// ---------------- MMA / ldmatrix wrappers ----------------
DEVINL void ldsm4(uint32_t* r, uint32_t addr) {
  asm volatile("ldmatrix.sync.aligned.m8n8.x4.shared.b16 {%0,%1,%2,%3}, [%4];"
               : "=r"(r[0]), "=r"(r[1]), "=r"(r[2]), "=r"(r[3]) : "r"(addr));
}
DEVINL void ldsm4t(uint32_t* r, uint32_t addr) {
  asm volatile("ldmatrix.sync.aligned.m8n8.x4.trans.shared.b16 {%0,%1,%2,%3}, [%4];"
               : "=r"(r[0]), "=r"(r[1]), "=r"(r[2]), "=r"(r[3]) : "r"(addr));
}
// non-volatile — pure register op; lets ptxas schedule/interleave HMMAs.
DEVINL void mma16816(float* c, const uint32_t* a, uint32_t b0, uint32_t b1) {
  asm("mma.sync.aligned.m16n8k16.row.col.f32.bf16.bf16.f32 "
      "{%0,%1,%2,%3}, {%4,%5,%6,%7}, {%8,%9}, {%0,%1,%2,%3};"
      : "+f"(c[0]), "+f"(c[1]), "+f"(c[2]), "+f"(c[3])
      : "r"(a[0]), "r"(a[1]), "r"(a[2]), "r"(a[3]), "r"(b0), "r"(b1));
}

// ---------------- pre-pass: fp32 K,V -> bf16 hi/lo planes ----------------
__global__ void __launch_bounds__(256)
conv_kernel(const float* __restrict__ k, const float* __restrict__ v) {
  size_t i = (size_t)blockIdx.x * 256 + threadIdx.x;  // float4 index
  float4 a = ((const float4*)k)[i];
  float4 b = ((const float4*)v)[i];
  __nv_bfloat16 h0, h1, h2, h3, l0, l1, l2, l3;
  split2(a.x, h0, l0); split2(a.y, h1, l1); split2(a.z, h2, l2); split2(a.w, h3, l3);
  ((uint2*)g_KH)[i] = make_uint2(pack2(h0, h1), pack2(h2, h3));
  ((uint2*)g_KL)[i] = make_uint2(pack2(l0, l1), pack2(l2, l3));
  split2(b.x, h0, l0); split2(b.y, h1, l1); split2(b.z, h2, l2); split2(b.w, h3, l3);
  ((uint2*)g_VH)[i] = make_uint2(pack2(h0, h1), pack2(h2, h3));
  ((uint2*)g_VL)[i] = make_uint2(pack2(l0, l1), pack2(l2, l3));
}

__global__ void __launch_bounds__(NTHREADS, 1)
attn_mask_kernel(const float* __restrict__ q, const float* __restrict__ mask,
                 float* __restrict__ out) {
  extern __shared__ char smem[];
  const uint32_t sb = smem_u32(smem);
  const int tid = threadIdx.x, wid = tid >> 5, lane = tid & 31;
  const int bh = (int)blockIdx.z * Hh + (int)blockIdx.y;
  const int s0 = (int)blockIdx.x * TM;

  char* QH = smem;
  char* QL = smem + TILE_B;
  const uint32_t sKH = sb + 2 * TILE_B;
  const uint32_t sKL = sb + 3 * TILE_B;
  const uint32_t sVH = sb + 4 * TILE_B;
  const uint32_t sVL = sb + 5 * TILE_B;

  const __nv_bfloat16* kh = g_KH + (size_t)bh * Ss * Dd;
  const __nv_bfloat16* kl = g_KL + (size_t)bh * Ss * Dd;
  const __nv_bfloat16* vh = g_VH + (size_t)bh * Ss * Dd;
  const __nv_bfloat16* vl = g_VL + (size_t)bh * Ss * Dd;

  // ---- load + split Q tile (once) ----
  {
    const float4* qsrc = (const float4*)(q + ((size_t)bh * Ss + s0) * Dd);
#pragma unroll
    for (int i = 0; i < 16; ++i) {
      int f = tid + i * NTHREADS;
      float4 val = qsrc[f];
      int e = f * 4;
      store_hl4(QH, QL, e >> 7, e & 127, val);
    }
  }

  // ---- prologue: async-load tile 0 K and V ----
  load_tile_pair(sKH, sKL, kh, kl, tid);
  CP_COMMIT();
  load_tile_pair(sVH, sVL, vh, vl, tid);
  CP_COMMIT();
  CP_WAIT1();          // K(0) done (V(0) may be in flight)
  __syncthreads();

  // warp tiling: wi = 32-row strip (4 strips), wj = t-half (64 cols)
  const int wi = wid >> 1;
  const int wj = wid & 1;
  const int wrow0 = wi * 32;
  const int tcol0 = wj * 64;

  // accumulators: S [2 m-frags][8 n-frags][4], O [2 m-frags][16 n-frags][4] (t-half partial)
  float S[2][8][4];
  float O[2][16][4];
#pragma unroll
  for (int mf = 0; mf < 2; ++mf)
#pragma unroll
    for (int i = 0; i < 16; ++i) { O[mf][i][0] = O[mf][i][1] = O[mf][i][2] = O[mf][i][3] = 0.f; }

  const int lrow = lane & 7;
  const int lq = (lane >> 3) & 1;
  const int lh = lane >> 4;

  // ldmatrix lane base addresses
  const uint32_t qA_h0 = sb + toff(wrow0 + lrow + lq * 8, lh * 8);
  const uint32_t qA_l0 = qA_h0 + TILE_B;
  const uint32_t qA_h1 = sb + toff(wrow0 + 16 + lrow + lq * 8, lh * 8);
  const uint32_t qA_l1 = qA_h1 + TILE_B;
  // K B-frags: t-rows from this warp's t-half
  const uint32_t kB_h = sKH + toff(tcol0 + lrow + lh * 8, lq * 8);
  const uint32_t kB_l = kB_h + TILE_B;
  // V B-frags (trans): t-rows from this warp's t-half, all 128 d-cols
  const uint32_t vB_h = sVH + toff(tcol0 + lrow + lq * 8, lh * 8);
  const uint32_t vB_l = vB_h + TILE_B;

  const int mr = wrow0 + (lane >> 2);      // thread's row within m-frag 0 (and +8/+16/+24)
  const int mc = (lane & 3) * 2;
  const float* mbase = mask + ((size_t)bh * Ss + (s0 + mr)) * Ss + tcol0;

#pragma unroll 1
  for (int kt = 0; kt < NKT; ++kt) {
    const int t0 = kt * TN;
    const int tn = (kt + 1 < NKT) ? (kt + 1) * TN : 0;  // clamp (harmless reload)

    // ---- GEMM1: S[32 x 64] = Q[strip] @ K[t-half]^T (3-term bf16 split) ----
#pragma unroll
    for (int mf = 0; mf < 2; ++mf)
#pragma unroll
      for (int i = 0; i < 8; ++i) { S[mf][i][0] = S[mf][i][1] = S[mf][i][2] = S[mf][i][3] = 0.f; }
#pragma unroll
    for (int kk = 0; kk < 8; ++kk) {
      uint32_t a0h[4], a0l[4], a1h[4], a1l[4];
      ldsm4(a0h, qA_h0 + kk * 32);
      ldsm4(a0l, qA_l0 + kk * 32);
      ldsm4(a1h, qA_h1 + kk * 32);
      ldsm4(a1l, qA_l1 + kk * 32);
#pragma unroll
      for (int ntp = 0; ntp < 4; ++ntp) {
        uint32_t bh_[4], bl_[4];
        ldsm4(bh_, kB_h + (uint32_t)(ntp * 16 * ROWB) + kk * 32);
        ldsm4(bl_, kB_l + (uint32_t)(ntp * 16 * ROWB) + kk * 32);
        mma16816(S[0][2 * ntp],     a0h, bh_[0], bh_[1]);
        mma16816(S[0][2 * ntp + 1], a0h, bh_[2], bh_[3]);
        mma16816(S[1][2 * ntp],     a1h, bh_[0], bh_[1]);
        mma16816(S[1][2 * ntp + 1], a1h, bh_[2], bh_[3]);
        mma16816(S[0][2 * ntp],     a0h, bl_[0], bl_[1]);
        mma16816(S[0][2 * ntp + 1], a0h, bl_[2], bl_[3]);
        mma16816(S[1][2 * ntp],     a1h, bl_[0], bl_[1]);
        mma16816(S[1][2 * ntp + 1], a1h, bl_[2], bl_[3]);
        mma16816(S[0][2 * ntp],     a0l, bh_[0], bh_[1]);
        mma16816(S[0][2 * ntp + 1], a0l, bh_[2], bh_[3]);
        mma16816(S[1][2 * ntp],     a1l, bh_[0], bh_[1]);
        mma16816(S[1][2 * ntp + 1], a1l, bh_[2], bh_[3]);
      }
    }

    __syncthreads();  // all warps done reading K tile

    // ---- issue next K tile (overlaps GEMM2) ----
    load_tile_pair(sKH, sKL, kh + (size_t)tn * Dd, kl + (size_t)tn * Dd, tid);
    CP_COMMIT();
    CP_WAIT1();       // V(kt) done (next-K outstanding)
    __syncthreads();

    // ---- GEMM2: O(partial) += (S*mask) @ V[t-half, :] ----
#pragma unroll
    for (int kk = 0; kk < 4; ++kk) {
      uint32_t ph[2][4], pl[2][4];
#pragma unroll
      for (int mf = 0; mf < 2; ++mf) {
        // mask this mf's n-frags 2kk, 2kk+1 (inline loads)
        const float* mrow = mbase + (size_t)(mf * 16) * Ss + t0;
        const float* mp0 = mrow + (2 * kk) * 8 + mc;
        const float* mp1 = mrow + (2 * kk + 1) * 8 + mc;
        float2 m0 = __ldcs((const float2*)mp0);
        float2 m1 = __ldcs((const float2*)(mp0 + 8 * Ss));
        float2 m2 = __ldcs((const float2*)mp1);
        float2 m3 = __ldcs((const float2*)(mp1 + 8 * Ss));
        float* s0v = S[mf][2 * kk];
        float* s1v = S[mf][2 * kk + 1];
        s0v[0] *= m0.x; s0v[1] *= m0.y; s0v[2] *= m1.x; s0v[3] *= m1.y;
        s1v[0] *= m2.x; s1v[1] *= m2.y; s1v[2] *= m3.x; s1v[3] *= m3.y;
        __nv_bfloat16 h0, h1, h2, h3, l0, l1, l2, l3;
        split2(s0v[0], h0, l0); split2(s0v[1], h1, l1);
        split2(s0v[2], h2, l2); split2(s0v[3], h3, l3);
        ph[mf][0] = pack2(h0, h1); ph[mf][1] = pack2(h2, h3);
        pl[mf][0] = pack2(l0, l1); pl[mf][1] = pack2(l2, l3);
        split2(s1v[0], h0, l0); split2(s1v[1], h1, l1);
        split2(s1v[2], h2, l2); split2(s1v[3], h3, l3);
        ph[mf][2] = pack2(h0, h1); ph[mf][3] = pack2(h2, h3);
        pl[mf][2] = pack2(l0, l1); pl[mf][3] = pack2(l2, l3);
      }
#pragma unroll
      for (int np = 0; np < 8; ++np) {
        uint32_t bh_[4], bl_[4];
        ldsm4t(bh_, vB_h + (uint32_t)(kk * 16 * ROWB) + np * 32);
        ldsm4t(bl_, vB_l + (uint32_t)(kk * 16 * ROWB) + np * 32);
        mma16816(O[0][2 * np],     ph[0], bh_[0], bh_[1]);
        mma16816(O[0][2 * np + 1], ph[0], bh_[2], bh_[3]);
        mma16816(O[1][2 * np],     ph[1], bh_[0], bh_[1]);
        mma16816(O[1][2 * np + 1], ph[1], bh_[2], bh_[3]);
        mma16816(O[0][2 * np],     ph[0], bl_[0], bl_[1]);
        mma16816(O[0][2 * np + 1], ph[0], bl_[2], bl_[3]);
        mma16816(O[1][2 * np],     ph[1], bl_[0], bl_[1]);
        mma16816(O[1][2 * np + 1], ph[1], bl_[2], bl_[3]);
        mma16816(O[0][2 * np],     pl[0], bh_[0], bh_[1]);
        mma16816(O[0][2 * np + 1], pl[0], bh_[2], bh_[3]);
        mma16816(O[1][2 * np],     pl[1], bh_[0], bh_[1]);
        mma16816(O[1][2 * np + 1], pl[1], bh_[2], bh_[3]);
      }
    }

    __syncthreads();  // all warps done reading V tile

    // ---- issue next V tile (overlaps next GEMM1) ----
    load_tile_pair(sVH, sVL, vh + (size_t)tn * Dd, vl + (size_t)tn * Dd, tid);
    CP_COMMIT();
    CP_WAIT1();       // next-K done (next-V outstanding)
    __syncthreads();
  }

  // ---- quiesce all outstanding cp.async before repurposing smem ----
  CP_WAIT0();
  __syncthreads();

  // ---- epilogue: combine t-half partial O via smem, then -> gmem ----
  {
    float* SP = (float*)(smem + 2 * TILE_B);   // K/V buffers dead; 128 x 132 floats
    if (wj == 1) {
#pragma unroll
      for (int mf = 0; mf < 2; ++mf) {
        const int r0 = mr + mf * 16;
#pragma unroll
        for (int nf = 0; nf < 16; ++nf) {
          SP[r0 * 132 + nf * 8 + mc]           = O[mf][nf][0];
          SP[r0 * 132 + nf * 8 + mc + 1]       = O[mf][nf][1];
          SP[(r0 + 8) * 132 + nf * 8 + mc]     = O[mf][nf][2];
          SP[(r0 + 8) * 132 + nf * 8 + mc + 1] = O[mf][nf][3];
        }
      }
    }
    __syncthreads();
    if (wj == 0) {
#pragma unroll
      for (int mf = 0; mf < 2; ++mf) {
        const int r0 = mr + mf * 16;
        float* ob = out + ((size_t)bh * Ss + (s0 + r0)) * Dd + mc;
#pragma unroll
        for (int nf = 0; nf < 16; ++nf) {
          float2 v0 = make_float2(O[mf][nf][0] + SP[r0 * 132 + nf * 8 + mc],
                                  O[mf][nf][1] + SP[r0 * 132 + nf * 8 + mc + 1]);
          float2 v1 = make_float2(O[mf][nf][2] + SP[(r0 + 8) * 132 + nf * 8 + mc],
                                  O[mf][nf][3] + SP[(r0 + 8) * 132 + nf * 8 + mc + 1]);
          *(float2*)(ob + nf * 8) = v0;
          *(float2*)(ob + 8 * Dd + nf * 8) = v1;
        }
      }
    }
  }
}

}  // namespace

extern "C" void kernel_launch(void* const* d_in, const int* in_sizes, int n_in,
                              void* d_out, int out_size) {
  (void)in_sizes; (void)n_in; (void)out_size;
  const float* q = (const float*)d_in[0];
  const float* k = (const float*)d_in[1];
  const float* v = (const float*)d_in[2];
  const float* m = (const float*)d_in[3];
  float* out = (float*)d_out;

  // pre-pass: convert K, V to bf16 hi/lo planes (NELEM/4 float4s, 256 thr/blk)
  conv_kernel<<<(int)(NELEM / 4 / 256), 256>>>(k, v);

  cudaFuncSetAttribute(attn_mask_kernel, cudaFuncAttributeMaxDynamicSharedMemorySize,
                       SMEM_BYTES);
  dim3 grid(Ss / TM, Hh, Bb);
  attn_mask_kernel<<<grid, NTHREADS, SMEM_BYTES>>>(q, m, out);
}

// round 14
// speedup vs baseline: 1.4368x; 1.4368x over previous
#include <cuda_runtime.h>
#include <cuda_fp16.h>
#include <cstdint>

#define DEVINL __device__ __forceinline__

namespace {

constexpr int Bb = 2, Hh = 16, Ss = 2048, Dd = 128;
constexpr int TM = 128;           // query tile
constexpr int TN = 128;           // key tile
constexpr int NKT = Ss / TN;      // 16
constexpr int NTHREADS = 256;     // 8 warps, 16 rows each
constexpr int ROWB = 272;         // 128 fp16 * 2B + 16B pad (conflict-free ldmatrix)
constexpr int TILE_B = 128 * ROWB;            // 34816
// planes: QH QL K0 K1 V0 V1
constexpr uint32_t SMEM_BYTES = 6 * TILE_B;   // 208896

constexpr size_t NELEM = (size_t)Bb * Hh * Ss * Dd;  // 8,388,608 per tensor

}  // namespace

// 32 MB of pre-rounded fp16 K and V (static scratch — legal)
__device__ __align__(16) __half g_K[NELEM];
__device__ __align__(16) __half g_V[NELEM];

namespace {

DEVINL uint32_t smem_u32(const void* p) {
  uint32_t a;
  asm("{ .reg .u64 t; cvta.to.shared.u64 t, %1; cvt.u32.u64 %0, t; }" : "=r"(a) : "l"(p));
  return a;
}

DEVINL uint32_t toff(int r, int c) { return (uint32_t)(r * ROWB + c * 2); }

// ---------------- fp32 -> fp16 hi/lo split ----------------
DEVINL void split2h(float x, __half& h, __half& l) {
  h = __float2half_rn(x);
  l = __float2half_rn(x - __half2float(h));
}
DEVINL uint32_t pack2h(__half lo_el, __half hi_el) {
  return ((uint32_t)__half_as_ushort(hi_el) << 16) | (uint32_t)__half_as_ushort(lo_el);
}

// store 4 consecutive cols of one row into hi/lo Q tiles (8B chunks)
DEVINL void store_q4(char* hB, char* lB, int row, int col, float4 val) {
  __half h0, h1, h2, h3, l0, l1, l2, l3;
  split2h(val.x, h0, l0); split2h(val.y, h1, l1);
  split2h(val.z, h2, l2); split2h(val.w, h3, l3);
  uint32_t off = toff(row, col);
  *reinterpret_cast<uint2*>(hB + off) = make_uint2(pack2h(h0, h1), pack2h(h2, h3));
  *reinterpret_cast<uint2*>(lB + off) = make_uint2(pack2h(l0, l1), pack2h(l2, l3));
}

// ---------------- cp.async helpers ----------------
DEVINL void cp16(uint32_t dst, const void* src) {
  asm volatile("cp.async.cg.shared.global [%0], [%1], 16;" :: "r"(dst), "l"(src));
}
#define CP_COMMIT()  asm volatile("cp.async.commit_group;" ::: "memory")
#define CP_WAIT3()   asm volatile("cp.async.wait_group 3;" ::: "memory")
#define CP_WAIT0()   asm volatile("cp.async.wait_group 0;" ::: "memory")

// copy one [128 x 128] fp16 tile gmem -> padded smem (8 cp.async/thread)
DEVINL void load_tile(uint32_t dst, const __half* src, int tid) {
#pragma unroll
  for (int i = 0; i < 8; ++i) {
    int c = tid + i * NTHREADS;       // chunk id: 2048 chunks of 16B
    int row = c >> 4, ch = c & 15;
    cp16(dst + (uint32_t)(row * ROWB + ch * 16), src + row * Dd + ch * 8);
  }
}

// ---------------- MMA / ldmatrix wrappers ----------------
DEVINL void ldsm4(uint32_t* r, uint32_t addr) {
  asm volatile("ldmatrix.sync.aligned.m8n8.x4.shared.b16 {%0,%1,%2,%3}, [%4];"
               : "=r"(r[0]), "=r"(r[1]), "=r"(r[2]), "=r"(r[3]) : "r"(addr));
}
DEVINL void ldsm4t(uint32_t* r, uint32_t addr) {
  asm volatile("ldmatrix.sync.aligned.m8n8.x4.trans.shared.b16 {%0,%1,%2,%3}, [%4];"
               : "=r"(r[0]), "=r"(r[1]), "=r"(r[2]), "=r"(r[3]) : "r"(addr));
}
// fp16 inputs, fp32 accum; non-volatile so ptxas can schedule.
DEVINL void mma16816(float* c, const uint32_t* a, uint32_t b0, uint32_t b1) {
  asm("mma.sync.aligned.m16n8k16.row.col.f32.f16.f16.f32 "
      "{%0,%1,%2,%3}, {%4,%5,%6,%7}, {%8,%9}, {%0,%1,%2,%3};"
      : "+f"(c[0]), "+f"(c[1]), "+f"(c[2]), "+f"(c[3])
      : "r"(a[0]), "r"(a[1]), "r"(a[2]), "r"(a[3]), "r"(b0), "r"(b1));
}

// ---------------- pre-pass: fp32 K,V -> fp16 (rounded once) ----------------
__global__ void __launch_bounds__(256)
conv_kernel(const float* __restrict__ k, const float* __restrict__ v) {
  size_t i = (size_t)blockIdx.x * 256 + threadIdx.x;  // float4 index
  float4 a = ((const float4*)k)[i];
  float4 b = ((const float4*)v)[i];
  ((uint2*)g_K)[i] = make_uint2(
      pack2h(__float2half_rn(a.x), __float2half_rn(a.y)),
      pack2h(__float2half_rn(a.z), __float2half_rn(a.w)));
  ((uint2*)g_V)[i] = make_uint2(
      pack2h(__float2half_rn(b.x), __float2half_rn(b.y)),
      pack2h(__float2half_rn(b.z), __float2half_rn(b.w)));
}

__global__ void __launch_bounds__(NTHREADS, 1)
attn_mask_kernel(const float* __restrict__ q, const float* __restrict__ mask,
                 float* __restrict__ out) {
  extern __shared__ char smem[];
  const uint32_t sb = smem_u32(smem);
  const int tid = threadIdx.x, wid = tid >> 5, lane = tid & 31;
  const int bh = (int)blockIdx.z * Hh + (int)blockIdx.y;
  const int s0 = (int)blockIdx.x * TM;

  char* QH = smem;
  char* QL = smem + TILE_B;
  // K buffers at planes 2,3; V buffers at planes 4,5

  const __half* kg = g_K + (size_t)bh * Ss * Dd;
  const __half* vg = g_V + (size_t)bh * Ss * Dd;

  // ---- prologue: async-load K(0),V(0),K(1),V(1) (4 groups) ----
  load_tile(sb + 2 * TILE_B, kg, tid);                    CP_COMMIT();
  load_tile(sb + 4 * TILE_B, vg, tid);                    CP_COMMIT();
  load_tile(sb + 3 * TILE_B, kg + (size_t)TN * Dd, tid);  CP_COMMIT();
  load_tile(sb + 5 * TILE_B, vg + (size_t)TN * Dd, tid);  CP_COMMIT();

  // ---- load + split Q tile (overlaps the async copies) ----
  {
    const float4* qsrc = (const float4*)(q + ((size_t)bh * Ss + s0) * Dd);
#pragma unroll
    for (int i = 0; i < 16; ++i) {
      int f = tid + i * NTHREADS;
      float4 val = qsrc[f];
      int e = f * 4;
      store_q4(QH, QL, e >> 7, e & 127, val);
    }
  }

  // accumulators
  float S[16][4];
  float O[16][4];
#pragma unroll
  for (int i = 0; i < 16; ++i) { O[i][0] = O[i][1] = O[i][2] = O[i][3] = 0.f; }

  const int wrow0 = wid * 16;
  const int lrow = lane & 7;
  const int lq = (lane >> 3) & 1;
  const int lh = lane >> 4;

  // ldmatrix lane base addresses
  const uint32_t qA_h = sb + toff(wrow0 + lrow + lq * 8, lh * 8);
  const uint32_t qA_l = qA_h + TILE_B;
  const uint32_t kB[2] = {sb + 2 * TILE_B + toff(lrow + lh * 8, lq * 8),
                          sb + 3 * TILE_B + toff(lrow + lh * 8, lq * 8)};
  const uint32_t vB[2] = {sb + 4 * TILE_B + toff(lrow + lq * 8, lh * 8),
                          sb + 5 * TILE_B + toff(lrow + lq * 8, lh * 8)};

  const int mr = wrow0 + (lane >> 2);      // this thread's row (and +8)
  const int mc = (lane & 3) * 2;
  const float* mbase = mask + ((size_t)bh * Ss + (s0 + mr)) * Ss;

#pragma unroll 1
  for (int kt = 0; kt < NKT; ++kt) {
    const int t0 = kt * TN;
    const int buf = kt & 1;
    const int t2 = (kt + 2 < NKT) ? (kt + 2) : 0;  // clamp (harmless reload)

    // ---- K(kt) ready: at most 3 newer groups outstanding ----
    CP_WAIT3();
    __syncthreads();

    // ---- GEMM1: S = Q @ K^T (fp16 2-term: Qhi,Qlo x Krounded) ----
#pragma unroll
    for (int i = 0; i < 16; ++i) { S[i][0] = S[i][1] = S[i][2] = S[i][3] = 0.f; }
#pragma unroll
    for (int kk = 0; kk < 8; ++kk) {
      uint32_t ah[4], al[4];
      ldsm4(ah, qA_h + kk * 32);
      ldsm4(al, qA_l + kk * 32);
#pragma unroll
      for (int ntp = 0; ntp < 8; ++ntp) {
        uint32_t b_[4];
        ldsm4(b_, kB[buf] + (uint32_t)(ntp * 16 * ROWB) + kk * 32);
        mma16816(S[2 * ntp],     ah, b_[0], b_[1]);
        mma16816(S[2 * ntp + 1], ah, b_[2], b_[3]);
        mma16816(S[2 * ntp],     al, b_[0], b_[1]);
        mma16816(S[2 * ntp + 1], al, b_[2], b_[3]);
      }
    }

    __syncthreads();  // all warps done reading K buf

    // ---- issue K(kt+2) into this K buffer (overlaps GEMM2) ----
    load_tile(kB[buf] - toff(lrow + lh * 8, lq * 8), kg + (size_t)t2 * TN * Dd, tid);
    CP_COMMIT();
    CP_WAIT3();       // V(kt) complete
    __syncthreads();

    // ---- GEMM2: O += (S*mask) @ V (fp16 2-term: Phi,Plo x Vrounded) ----
#pragma unroll
    for (int kk = 0; kk < 8; ++kk) {
      // mask n-frags 2kk, 2kk+1 (streamed)
      {
        const float* mp0 = mbase + t0 + (2 * kk) * 8 + mc;
        const float* mp1 = mbase + t0 + (2 * kk + 1) * 8 + mc;
        float2 m0 = __ldcs((const float2*)mp0);
        float2 m1 = __ldcs((const float2*)(mp0 + 8 * Ss));
        float2 m2 = __ldcs((const float2*)mp1);
        float2 m3 = __ldcs((const float2*)(mp1 + 8 * Ss));
        S[2 * kk][0] *= m0.x;     S[2 * kk][1] *= m0.y;
        S[2 * kk][2] *= m1.x;     S[2 * kk][3] *= m1.y;
        S[2 * kk + 1][0] *= m2.x; S[2 * kk + 1][1] *= m2.y;
        S[2 * kk + 1][2] *= m3.x; S[2 * kk + 1][3] *= m3.y;
      }
      // build P A-fragments (fp16 hi/lo) from S n-frags 2kk, 2kk+1
      uint32_t ph[4], pl[4];
      {
        __half h0, h1, h2, h3, l0, l1, l2, l3;
        split2h(S[2 * kk][0], h0, l0); split2h(S[2 * kk][1], h1, l1);
        split2h(S[2 * kk][2], h2, l2); split2h(S[2 * kk][3], h3, l3);
        ph[0] = pack2h(h0, h1); ph[1] = pack2h(h2, h3);
        pl[0] = pack2h(l0, l1); pl[1] = pack2h(l2, l3);
        split2h(S[2 * kk + 1][0], h0, l0); split2h(S[2 * kk + 1][1], h1, l1);
        split2h(S[2 * kk + 1][2], h2, l2); split2h(S[2 * kk + 1][3], h3, l3);
        ph[2] = pack2h(h0, h1); ph[3] = pack2h(h2, h3);
        pl[2] = pack2h(l0, l1); pl[3] = pack2h(l2, l3);
      }
#pragma unroll
      for (int np = 0; np < 8; ++np) {
        uint32_t b_[4];
        ldsm4t(b_, vB[buf] + (uint32_t)(kk * 16 * ROWB) + np * 32);
        mma16816(O[2 * np],     ph, b_[0], b_[1]);
        mma16816(O[2 * np + 1], ph, b_[2], b_[3]);
        mma16816(O[2 * np],     pl, b_[0], b_[1]);
        mma16816(O[2 * np + 1], pl, b_[2], b_[3]);
      }
    }

    __syncthreads();  // all warps done reading V buf

    // ---- issue V(kt+2) into this V buffer (overlaps next GEMM1) ----
    load_tile(vB[buf] - toff(lrow + lq * 8, lh * 8), vg + (size_t)t2 * TN * Dd, tid);
    CP_COMMIT();
  }

  CP_WAIT0();  // quiesce outstanding tail loads before exit

  // ---- epilogue: O regs -> gmem ----
  {
    float* ob = out + ((size_t)bh * Ss + (s0 + mr)) * Dd + mc;
#pragma unroll
    for (int nf = 0; nf < 16; ++nf) {
      *(float2*)(ob + nf * 8) = make_float2(O[nf][0], O[nf][1]);
      *(float2*)(ob + 8 * Dd + nf * 8) = make_float2(O[nf][2], O[nf][3]);
    }
  }
}

}  // namespace

extern "C" void kernel_launch(void* const* d_in, const int* in_sizes, int n_in,
                              void* d_out, int out_size) {
  (void)in_sizes; (void)n_in; (void)out_size;
  const float* q = (const float*)d_in[0];
  const float* k = (const float*)d_in[1];
  const float* v = (const float*)d_in[2];
  const float* m = (const float*)d_in[3];
  float* out = (float*)d_out;

  // pre-pass: round K, V to fp16 (NELEM/4 float4s, 256 thr/blk)
  conv_kernel<<<(int)(NELEM / 4 / 256), 256>>>(k, v);

  cudaFuncSetAttribute(attn_mask_kernel, cudaFuncAttributeMaxDynamicSharedMemorySize,
                       SMEM_BYTES);
  dim3 grid(Ss / TM, Hh, Bb);
  attn_mask_kernel<<<grid, NTHREADS, SMEM_BYTES>>>(q, m, out);
}

// round 15
// speedup vs baseline: 1.9017x; 1.3236x over previous
#include <cuda_runtime.h>
#include <cuda_fp16.h>
#include <cstdint>

#define DEVINL __device__ __forceinline__

namespace {

constexpr int Bb = 2, Hh = 16, Ss = 2048, Dd = 128;
constexpr int TM = 128;           // query tile
constexpr int TN = 128;           // key tile
constexpr int NKT = Ss / TN;      // 16
constexpr int NTHREADS = 256;     // 8 warps, 16 rows each
constexpr int ROWB = 272;         // 128 fp16 * 2B + 16B pad (conflict-free ldmatrix)
constexpr int TILE_B = 128 * ROWB;            // 34816
// planes: Q K0 K1 V0 V1
constexpr uint32_t SMEM_BYTES = 5 * TILE_B;   // 174080

constexpr size_t NELEM = (size_t)Bb * Hh * Ss * Dd;  // 8,388,608 per tensor

}  // namespace

// 32 MB of pre-rounded fp16 K and V (static scratch — legal)
__device__ __align__(16) __half g_K[NELEM];
__device__ __align__(16) __half g_V[NELEM];

namespace {

DEVINL uint32_t smem_u32(const void* p) {
  uint32_t a;
  asm("{ .reg .u64 t; cvta.to.shared.u64 t, %1; cvt.u32.u64 %0, t; }" : "=r"(a) : "l"(p));
  return a;
}

DEVINL uint32_t toff(int r, int c) { return (uint32_t)(r * ROWB + c * 2); }

DEVINL uint32_t pack2h(__half lo_el, __half hi_el) {
  return ((uint32_t)__half_as_ushort(hi_el) << 16) | (uint32_t)__half_as_ushort(lo_el);
}

// ---------------- cp.async helpers ----------------
DEVINL void cp16(uint32_t dst, const void* src) {
  asm volatile("cp.async.cg.shared.global [%0], [%1], 16;" :: "r"(dst), "l"(src));
}
#define CP_COMMIT()  asm volatile("cp.async.commit_group;" ::: "memory")
#define CP_WAIT3()   asm volatile("cp.async.wait_group 3;" ::: "memory")
#define CP_WAIT0()   asm volatile("cp.async.wait_group 0;" ::: "memory")

// copy one [128 x 128] fp16 tile gmem -> padded smem (8 cp.async/thread)
DEVINL void load_tile(uint32_t dst, const __half* src, int tid) {
#pragma unroll
  for (int i = 0; i < 8; ++i) {
    int c = tid + i * NTHREADS;       // chunk id: 2048 chunks of 16B
    int row = c >> 4, ch = c & 15;
    cp16(dst + (uint32_t)(row * ROWB + ch * 16), src + row * Dd + ch * 8);
  }
}

// ---------------- MMA / ldmatrix wrappers ----------------
DEVINL void ldsm4(uint32_t* r, uint32_t addr) {
  asm volatile("ldmatrix.sync.aligned.m8n8.x4.shared.b16 {%0,%1,%2,%3}, [%4];"
               : "=r"(r[0]), "=r"(r[1]), "=r"(r[2]), "=r"(r[3]) : "r"(addr));
}
DEVINL void ldsm4t(uint32_t* r, uint32_t addr) {
  asm volatile("ldmatrix.sync.aligned.m8n8.x4.trans.shared.b16 {%0,%1,%2,%3}, [%4];"
               : "=r"(r[0]), "=r"(r[1]), "=r"(r[2]), "=r"(r[3]) : "r"(addr));
}
// fp16 inputs, fp32 accum; non-volatile so ptxas can schedule.
DEVINL void mma16816(float* c, const uint32_t* a, uint32_t b0, uint32_t b1) {
  asm("mma.sync.aligned.m16n8k16.row.col.f32.f16.f16.f32 "
      "{%0,%1,%2,%3}, {%4,%5,%6,%7}, {%8,%9}, {%0,%1,%2,%3};"
      : "+f"(c[0]), "+f"(c[1]), "+f"(c[2]), "+f"(c[3])
      : "r"(a[0]), "r"(a[1]), "r"(a[2]), "r"(a[3]), "r"(b0), "r"(b1));
}

// ---------------- pre-pass: fp32 K,V -> fp16 (rounded once) ----------------
__global__ void __launch_bounds__(256)
conv_kernel(const float* __restrict__ k, const float* __restrict__ v) {
  size_t i = (size_t)blockIdx.x * 256 + threadIdx.x;  // float4 index
  float4 a = ((const float4*)k)[i];
  float4 b = ((const float4*)v)[i];
  ((uint2*)g_K)[i] = make_uint2(
      pack2h(__float2half_rn(a.x), __float2half_rn(a.y)),
      pack2h(__float2half_rn(a.z), __float2half_rn(a.w)));
  ((uint2*)g_V)[i] = make_uint2(
      pack2h(__float2half_rn(b.x), __float2half_rn(b.y)),
      pack2h(__float2half_rn(b.z), __float2half_rn(b.w)));
}

__global__ void __launch_bounds__(NTHREADS, 1)
attn_mask_kernel(const float* __restrict__ q, const float* __restrict__ mask,
                 float* __restrict__ out) {
  extern __shared__ char smem[];
  const uint32_t sb = smem_u32(smem);
  const int tid = threadIdx.x, wid = tid >> 5, lane = tid & 31;
  const int bh = (int)blockIdx.z * Hh + (int)blockIdx.y;
  const int s0 = (int)blockIdx.x * TM;

  char* QF = smem;  // single fp16 Q plane
  // K buffers at planes 1,2; V buffers at planes 3,4

  const __half* kg = g_K + (size_t)bh * Ss * Dd;
  const __half* vg = g_V + (size_t)bh * Ss * Dd;

  // ---- prologue: async-load K(0),V(0),K(1),V(1) (4 groups) ----
  load_tile(sb + 1 * TILE_B, kg, tid);                    CP_COMMIT();
  load_tile(sb + 3 * TILE_B, vg, tid);                    CP_COMMIT();
  load_tile(sb + 2 * TILE_B, kg + (size_t)TN * Dd, tid);  CP_COMMIT();
  load_tile(sb + 4 * TILE_B, vg + (size_t)TN * Dd, tid);  CP_COMMIT();

  // ---- load + round Q tile to fp16 (overlaps the async copies) ----
  {
    const float4* qsrc = (const float4*)(q + ((size_t)bh * Ss + s0) * Dd);
#pragma unroll
    for (int i = 0; i < 16; ++i) {
      int f = tid + i * NTHREADS;
      float4 val = qsrc[f];
      int e = f * 4;
      uint32_t off = toff(e >> 7, e & 127);
      *reinterpret_cast<uint2*>(QF + off) = make_uint2(
          pack2h(__float2half_rn(val.x), __float2half_rn(val.y)),
          pack2h(__float2half_rn(val.z), __float2half_rn(val.w)));
    }
  }

  // accumulators
  float S[16][4];
  float O[16][4];
#pragma unroll
  for (int i = 0; i < 16; ++i) { O[i][0] = O[i][1] = O[i][2] = O[i][3] = 0.f; }

  const int wrow0 = wid * 16;
  const int lrow = lane & 7;
  const int lq = (lane >> 3) & 1;
  const int lh = lane >> 4;

  // ldmatrix lane base addresses
  const uint32_t qA = sb + toff(wrow0 + lrow + lq * 8, lh * 8);
  const uint32_t kB[2] = {sb + 1 * TILE_B + toff(lrow + lh * 8, lq * 8),
                          sb + 2 * TILE_B + toff(lrow + lh * 8, lq * 8)};
  const uint32_t vB[2] = {sb + 3 * TILE_B + toff(lrow + lq * 8, lh * 8),
                          sb + 4 * TILE_B + toff(lrow + lq * 8, lh * 8)};

  const int mr = wrow0 + (lane >> 2);      // this thread's row (and +8)
  const int mc = (lane & 3) * 2;
  const float* mbase = mask + ((size_t)bh * Ss + (s0 + mr)) * Ss;

#pragma unroll 1
  for (int kt = 0; kt < NKT; ++kt) {
    const int t0 = kt * TN;
    const int buf = kt & 1;
    const int t2 = (kt + 2 < NKT) ? (kt + 2) : 0;  // clamp (harmless reload)

    // ---- K(kt) ready: at most 3 newer groups outstanding ----
    CP_WAIT3();
    __syncthreads();

    // ---- GEMM1: S = Q @ K^T (fp16 single-term) ----
#pragma unroll
    for (int i = 0; i < 16; ++i) { S[i][0] = S[i][1] = S[i][2] = S[i][3] = 0.f; }
#pragma unroll
    for (int kk = 0; kk < 8; ++kk) {
      uint32_t a_[4];
      ldsm4(a_, qA + kk * 32);
#pragma unroll
      for (int ntp = 0; ntp < 8; ++ntp) {
        uint32_t b_[4];
        ldsm4(b_, kB[buf] + (uint32_t)(ntp * 16 * ROWB) + kk * 32);
        mma16816(S[2 * ntp],     a_, b_[0], b_[1]);
        mma16816(S[2 * ntp + 1], a_, b_[2], b_[3]);
      }
    }

    __syncthreads();  // all warps done reading K buf

    // ---- issue K(kt+2) into this K buffer (overlaps GEMM2) ----
    load_tile(kB[buf] - toff(lrow + lh * 8, lq * 8), kg + (size_t)t2 * TN * Dd, tid);
    CP_COMMIT();
    CP_WAIT3();       // V(kt) complete
    __syncthreads();

    // ---- GEMM2: O += (S*mask) @ V (fp16 single-term P) ----
#pragma unroll
    for (int kk = 0; kk < 8; ++kk) {
      // mask n-frags 2kk, 2kk+1 (streamed)
      {
        const float* mp0 = mbase + t0 + (2 * kk) * 8 + mc;
        const float* mp1 = mbase + t0 + (2 * kk + 1) * 8 + mc;
        float2 m0 = __ldcs((const float2*)mp0);
        float2 m1 = __ldcs((const float2*)(mp0 + 8 * Ss));
        float2 m2 = __ldcs((const float2*)mp1);
        float2 m3 = __ldcs((const float2*)(mp1 + 8 * Ss));
        S[2 * kk][0] *= m0.x;     S[2 * kk][1] *= m0.y;
        S[2 * kk][2] *= m1.x;     S[2 * kk][3] *= m1.y;
        S[2 * kk + 1][0] *= m2.x; S[2 * kk + 1][1] *= m2.y;
        S[2 * kk + 1][2] *= m3.x; S[2 * kk + 1][3] *= m3.y;
      }
      // build P A-fragment (rounded fp16) from S n-frags 2kk, 2kk+1
      uint32_t ph[4];
      ph[0] = pack2h(__float2half_rn(S[2 * kk][0]), __float2half_rn(S[2 * kk][1]));
      ph[1] = pack2h(__float2half_rn(S[2 * kk][2]), __float2half_rn(S[2 * kk][3]));
      ph[2] = pack2h(__float2half_rn(S[2 * kk + 1][0]), __float2half_rn(S[2 * kk + 1][1]));
      ph[3] = pack2h(__float2half_rn(S[2 * kk + 1][2]), __float2half_rn(S[2 * kk + 1][3]));
#pragma unroll
      for (int np = 0; np < 8; ++np) {
        uint32_t b_[4];
        ldsm4t(b_, vB[buf] + (uint32_t)(kk * 16 * ROWB) + np * 32);
        mma16816(O[2 * np],     ph, b_[0], b_[1]);
        mma16816(O[2 * np + 1], ph, b_[2], b_[3]);
      }
    }

    __syncthreads();  // all warps done reading V buf

    // ---- issue V(kt+2) into this V buffer (overlaps next GEMM1) ----
    load_tile(vB[buf] - toff(lrow + lq * 8, lh * 8), vg + (size_t)t2 * TN * Dd, tid);
    CP_COMMIT();
  }

  CP_WAIT0();  // quiesce outstanding tail loads before exit

  // ---- epilogue: O regs -> gmem ----
  {
    float* ob = out + ((size_t)bh * Ss + (s0 + mr)) * Dd + mc;
#pragma unroll
    for (int nf = 0; nf < 16; ++nf) {
      *(float2*)(ob + nf * 8) = make_float2(O[nf][0], O[nf][1]);
      *(float2*)(ob + 8 * Dd + nf * 8) = make_float2(O[nf][2], O[nf][3]);
    }
  }
}

}  // namespace

extern "C" void kernel_launch(void* const* d_in, const int* in_sizes, int n_in,
                              void* d_out, int out_size) {
  (void)in_sizes; (void)n_in; (void)out_size;
  const float* q = (const float*)d_in[0];
  const float* k = (const float*)d_in[1];
  const float* v = (const float*)d_in[2];
  const float* m = (const float*)d_in[3];
  float* out = (float*)d_out;

  // pre-pass: round K, V to fp16 (NELEM/4 float4s, 256 thr/blk)
  conv_kernel<<<(int)(NELEM / 4 / 256), 256>>>(k, v);

  cudaFuncSetAttribute(attn_mask_kernel, cudaFuncAttributeMaxDynamicSharedMemorySize,
                       SMEM_BYTES);
  dim3 grid(Ss / TM, Hh, Bb);
  attn_mask_kernel<<<grid, NTHREADS, SMEM_BYTES>>>(q, m, out);
}